// round 4
// baseline (speedup 1.0000x reference)
#include <cuda_runtime.h>
#include <cstdint>

// ============================================================================
// SpikingReservoirLoaded: B=64, T=500, R=2048, beta=0.9, thr=1.0, zero reset.
//   V_t = beta*V_{t-1} + x[b,t]*w_in[r] + sum_{j: S_{t-1}[b,j]=1} W[j,r]
//   S_t = (V_t >= 1);  V_t = 0 where spiked (reset BEFORE recording)
// Outputs (assumed concat): [avg_rate(1), spike_record(T*B*R), mem_record(T*B*R)]
//
// Strategy: ONE persistent kernel, 128 CTAs x 512 threads (co-resident on
// 148-SM GB300). Spikes exchanged as 64-word bitmasks per batch (double-
// buffered by step parity). Software chip barrier via per-CTA flag array.
// Warp mapping: warp gw -> batch b = gw&63, colgroup cg = gw>>6, so a CTA's
// 16 warps share one 64-column W slice across 16 batches -> L1 reuse, L2
// traffic ~= one W sweep per step instead of 10x that.
// ============================================================================

#define T_STEPS   500
#define BATCH     64
#define RSIZE     2048
#define NWORDS    (RSIZE / 32)      // 64 mask words per batch
#define NBLOCKS   128
#define NTHREADS  512
#define TBR       (500LL * 64LL * 2048LL)   // 65,536,000

__device__ unsigned g_masks[2][BATCH][NWORDS];   // spike bitmasks, ping-pong
__device__ volatile unsigned g_flags[NBLOCKS];   // software barrier flags
__device__ unsigned long long g_spike_count;

// Zero state each graph replay (runs before the main kernel on the stream).
__global__ void snn_init_kernel() {
    int t = threadIdx.x;
    // zero only buffer 0 (read at step 0: S0 = 0)
    for (int i = t; i < BATCH * NWORDS; i += blockDim.x)
        (&g_masks[0][0][0])[i] = 0u;
    if (t < NBLOCKS) g_flags[t] = 0u;
    if (t == 0) g_spike_count = 0ull;
}

// Bit interleave: 16 low bits of x spread to even bit positions.
__device__ __forceinline__ unsigned part1by1(unsigned x) {
    x &= 0xFFFFu;
    x = (x | (x << 8)) & 0x00FF00FFu;
    x = (x | (x << 4)) & 0x0F0F0F0Fu;
    x = (x | (x << 2)) & 0x33333333u;
    x = (x | (x << 1)) & 0x55555555u;
    return x;
}
// word bit 2l from a's bit l, bit 2l+1 from b's bit l
__device__ __forceinline__ unsigned interleave16(unsigned a, unsigned b) {
    return part1by1(a) | (part1by1(b) << 1);
}

__global__ void __launch_bounds__(NTHREADS, 1)
snn_kernel(const float* __restrict__ x,      // (B, T)   [B,T,1]
           const float* __restrict__ w_in,   // (R)
           const float* __restrict__ W,      // (R, R) row-major: W[j*R + r]
           float* spike_out,                 // (T,B,R) or null
           float* mem_out,                   // (T,B,R) or null
           float* avg_out)                   // scalar or null
{
    const int lane      = threadIdx.x & 31;
    const int warpInBlk = threadIdx.x >> 5;
    const int gw = blockIdx.x * (NTHREADS / 32) + warpInBlk;   // 0..2047
    const int b  = gw & 63;        // batch
    const int cg = gw >> 6;        // column group, 0..31 (64 cols each)
    const int ch = cg * 32 + lane; // float2 column index; cols = 2ch, 2ch+1

    const float2* __restrict__ W2 = reinterpret_cast<const float2*>(W) + ch;
    const float2 win2 = reinterpret_cast<const float2*>(w_in)[ch];
    const float* __restrict__ xb = x + b * T_STEPS;

    float2 V = make_float2(0.0f, 0.0f);
    unsigned my_count = 0;
    const long long recBase = (long long)b * RSIZE + 2 * ch;

    for (int t = 0; t < T_STEPS; ++t) {
        // ---- load this batch's previous-step spike mask (64 words) ----
        const unsigned* mrd = &g_masks[t & 1][b][0];
        unsigned m0 = __ldcg(mrd + lane);        // words 0..31 across lanes
        unsigned m1 = __ldcg(mrd + 32 + lane);   // words 32..63

        // ---- sparse gather-sum of W rows for firing neurons ----
        float accx = 0.0f, accy = 0.0f;
        #pragma unroll 1
        for (int w = 0; w < NWORDS; ++w) {
            unsigned word = __shfl_sync(0xffffffffu, (w < 32) ? m0 : m1, w & 31);
            int jb = w << 5;
            while (word) {
                int j = jb + (__ffs(word) - 1);
                word &= word - 1;
                float2 wv = __ldg(&W2[(size_t)j * (RSIZE / 2)]);
                accx += wv.x;
                accy += wv.y;
            }
        }

        // ---- LIF update + threshold + zero reset ----
        float xv  = __ldg(xb + t);
        float vnx = fmaf(0.9f, V.x, xv * win2.x) + accx;
        float vny = fmaf(0.9f, V.y, xv * win2.y) + accy;
        bool s0 = (vnx >= 1.0f);
        bool s1 = (vny >= 1.0f);
        V.x = s0 ? 0.0f : vnx;
        V.y = s1 ? 0.0f : vny;
        my_count += (unsigned)s0 + (unsigned)s1;

        // ---- publish spike bitmask for next step (2 words per warp) ----
        unsigned bal0 = __ballot_sync(0xffffffffu, s0);
        unsigned bal1 = __ballot_sync(0xffffffffu, s1);
        if (lane == 0) {
            unsigned* mwrt = &g_masks[(t + 1) & 1][b][cg * 2];
            mwrt[0] = interleave16(bal0 & 0xFFFFu, bal1 & 0xFFFFu);
            mwrt[1] = interleave16(bal0 >> 16, bal1 >> 16);
        }

        // ---- record spikes + membrane (scalar stores: base may be 4B-aligned) ----
        if (spike_out) {
            long long off = (long long)t * (BATCH * RSIZE) + recBase;
            spike_out[off]     = s0 ? 1.0f : 0.0f;
            spike_out[off + 1] = s1 ? 1.0f : 0.0f;
            mem_out[off]     = V.x;
            mem_out[off + 1] = V.y;
        }

        // ---- chip-wide software barrier ----
        __threadfence();                         // release our mask/record stores
        __syncthreads();
        if (threadIdx.x == 0) g_flags[blockIdx.x] = (unsigned)(t + 1);
        if (threadIdx.x < NBLOCKS) {
            while (g_flags[threadIdx.x] < (unsigned)(t + 1)) { }
        }
        __threadfence();                         // acquire before next-step mask reads
        __syncthreads();
    }

    // ---- global spike count -> average firing rate ----
    #pragma unroll
    for (int s = 16; s; s >>= 1)
        my_count += __shfl_down_sync(0xffffffffu, my_count, s);
    if (lane == 0) atomicAdd(&g_spike_count, (unsigned long long)my_count);

    __threadfence();
    __syncthreads();
    if (threadIdx.x == 0) g_flags[blockIdx.x] = (unsigned)(T_STEPS + 1);

    if (blockIdx.x == 0) {
        if (threadIdx.x < NBLOCKS) {
            while (g_flags[threadIdx.x] < (unsigned)(T_STEPS + 1)) { }
        }
        __threadfence();
        __syncthreads();
        if (threadIdx.x == 0 && avg_out) {
            double cnt = (double)g_spike_count;
            *avg_out = (float)(cnt / (double)TBR);
        }
    }
}

extern "C" void kernel_launch(void* const* d_in, const int* in_sizes, int n_in,
                              void* d_out, int out_size) {
    (void)in_sizes; (void)n_in;
    const float* x    = (const float*)d_in[0];   // (64, 500, 1)
    const float* w_in = (const float*)d_in[1];   // (2048, 1)
    const float* W    = (const float*)d_in[2];   // (2048, 2048)
    float* out = (float*)d_out;

    float* spike = nullptr;
    float* mem   = nullptr;
    float* avg   = nullptr;
    const long long tbr = TBR;
    const long long osz = (long long)out_size;

    if (osz == 2 * tbr + 1) {            // [avg, spikes, mem]
        avg = out; spike = out + 1; mem = out + 1 + tbr;
    } else if (osz == 2 * tbr) {         // [spikes, mem]
        spike = out; mem = out + tbr;
    } else if (osz == 1) {               // scalar only
        avg = out;
    } else if (osz > 2 * tbr + 1) {      // unknown but big enough: assume concat
        avg = out; spike = out + 1; mem = out + 1 + tbr;
    } else {                             // unknown small: write what fits safely
        avg = out;
    }

    snn_init_kernel<<<1, 256>>>();
    snn_kernel<<<NBLOCKS, NTHREADS>>>(x, w_in, W, spike, mem, avg);
}

// round 7
// speedup vs baseline: 2.1177x; 2.1177x over previous
#include <cuda_runtime.h>
#include <cstdint>

// ============================================================================
// SpikingReservoirLoaded: B=64, T=500, R=2048, beta=0.9, thr=1.0, zero reset.
//   V_t = beta*V_{t-1} + x[b,t]*w_in[r] + sum_{j: S_{t-1}[b,j]=1} W[j,r]
//
// R6: same as R5 (CTA = 16-column W slice in padded SMEM, all 64 batches per
// CTA for load balance, full ascending-j scan with a single accumulator pair
// = bit-identical fp32 order to the verified R3 kernel), but the record
// stores are SCALAR: spike_out/mem_out bases are out+1 / out+1+TBR, i.e.
// only 4B-aligned, so float2 (STG.64) stores fault. That was R5's crash.
// ============================================================================

#define T_STEPS   500
#define BATCH     64
#define RSIZE     2048
#define NWORDS    64                      // 32-bit mask words per batch
#define NBLOCKS   128
#define NTHREADS  512
#define TBR       (500LL * 64LL * 2048LL) // 65,536,000

#define ROWSTRIDE 9                       // float2 slots per smem W row (72B, pad)
#define SMEM_W_BYTES   (RSIZE * ROWSTRIDE * 8)              // 147456
#define SMEM_MASK_OFF  (RSIZE * ROWSTRIDE)                  // in float2 units
#define SMEM_BYTES     (SMEM_W_BYTES + BATCH * NWORDS * 4)  // + 16384 = 163840

__device__ unsigned g_masks[2][BATCH][NWORDS];   // spike bitmasks, ping-pong
__device__ volatile unsigned g_flags[NBLOCKS];   // software barrier flags
__device__ unsigned long long g_spike_count;

__global__ void snn_init_kernel() {
    int t = threadIdx.x;
    for (int i = t; i < BATCH * NWORDS; i += blockDim.x)
        (&g_masks[0][0][0])[i] = 0u;               // S0 = 0 (read at step 0)
    if (t < NBLOCKS) g_flags[t] = 0u;
    if (t == 0) g_spike_count = 0ull;
}

__global__ void __launch_bounds__(NTHREADS, 1)
snn_kernel(const float* __restrict__ x,      // (B, T)   [B,T,1]
           const float* __restrict__ w_in,   // (R)
           const float* __restrict__ W,      // (R, R) row-major: W[j*R + r]
           float* __restrict__ spike_out,    // (T,B,R) or null (4B-aligned only!)
           float* __restrict__ mem_out,      // (T,B,R) or null (4B-aligned only!)
           float* avg_out)                   // scalar or null
{
    extern __shared__ float2 smem2[];
    float2* Ws2 = smem2;                                  // [2048][9] (use 8)
    unsigned long long* smask =
        reinterpret_cast<unsigned long long*>(smem2 + SMEM_MASK_OFF); // [64][32]

    const int tid = threadIdx.x;
    const int cta = blockIdx.x;
    const int b   = tid >> 3;           // batch 0..63
    const int p   = tid & 7;            // column pair 0..7
    const int col0 = cta * 16 + p * 2;  // this thread's even column

    // ---- load W column slice into smem (16 cols = 8 float2 per row) ----
    for (int idx = tid; idx < RSIZE * 8; idx += NTHREADS) {
        int j = idx >> 3, q = idx & 7;
        Ws2[j * ROWSTRIDE + q] =
            *reinterpret_cast<const float2*>(W + (size_t)j * RSIZE + cta * 16 + q * 2);
    }

    const float2 win2 = *reinterpret_cast<const float2*>(w_in + col0);
    const float* __restrict__ xb = x + b * T_STEPS;

    float2 V = make_float2(0.f, 0.f);
    unsigned cnt = 0;
    const long long recBase = (long long)b * RSIZE + col0;

    for (int t = 0; t < T_STEPS; ++t) {
        // ---- stage all batches' spike masks into smem (16KB from L2) ----
        {
            const uint4* src = reinterpret_cast<const uint4*>(&g_masks[t & 1][0][0]);
            uint4* dst = reinterpret_cast<uint4*>(smask);
            dst[tid]            = __ldcg(src + tid);
            dst[tid + NTHREADS] = __ldcg(src + tid + NTHREADS);
        }
        __syncthreads();

        // ---- sparse gather-sum: FULL ascending-j scan, single accumulators
        //      (bit-identical order to the verified R3 kernel) ----
        float ax = 0.f, ay = 0.f;
        const unsigned long long* mrow = smask + b * 32;
        #pragma unroll 1
        for (int c = 0; c < 32; ++c) {
            unsigned long long m = mrow[c];
            const int jb = c << 6;
            while (m) {
                int j = jb + (__ffsll((long long)m) - 1);
                m &= m - 1;
                float2 wv = Ws2[j * ROWSTRIDE + p];
                ax += wv.x;
                ay += wv.y;
            }
        }

        // ---- LIF update (identical formula to R3) ----
        float xv = __ldg(xb + t);
        float v0 = fmaf(0.9f, V.x, xv * win2.x) + ax;
        float v1 = fmaf(0.9f, V.y, xv * win2.y) + ay;
        bool s0 = (v0 >= 1.0f);
        bool s1 = (v1 >= 1.0f);
        V.x = s0 ? 0.f : v0;
        V.y = s1 ? 0.f : v1;
        cnt += (unsigned)s0 + (unsigned)s1;

        // ---- records: SCALAR stores (bases only 4B-aligned) ----
        if (spike_out) {
            long long off = (long long)t * (BATCH * RSIZE) + recBase;
            spike_out[off]     = s0 ? 1.f : 0.f;
            spike_out[off + 1] = s1 ? 1.f : 0.f;
            mem_out[off]     = V.x;
            mem_out[off + 1] = V.y;
        }

        // ---- publish 16-bit spike slice for (b, cta) ----
        unsigned hv = ((unsigned)s0 | ((unsigned)s1 << 1)) << (p * 2);
        hv |= __shfl_xor_sync(0xffffffffu, hv, 1);
        hv |= __shfl_xor_sync(0xffffffffu, hv, 2);
        hv |= __shfl_xor_sync(0xffffffffu, hv, 4);
        if (p == 0) {
            unsigned short* m16 =
                reinterpret_cast<unsigned short*>(&g_masks[(t + 1) & 1][0][0]);
            m16[b * 128 + cta] = (unsigned short)hv;  // word cta/2, half cta&1
        }

        // ---- chip-wide software barrier ----
        __threadfence();
        __syncthreads();
        if (tid == 0) g_flags[cta] = (unsigned)(t + 1);
        if (tid < NBLOCKS) {
            while (g_flags[tid] < (unsigned)(t + 1)) { }
        }
        __threadfence();
        __syncthreads();
    }

    // ---- global spike count -> average firing rate ----
    #pragma unroll
    for (int s = 16; s; s >>= 1)
        cnt += __shfl_down_sync(0xffffffffu, cnt, s);
    if ((tid & 31) == 0 && cnt) atomicAdd(&g_spike_count, (unsigned long long)cnt);

    __threadfence();
    __syncthreads();
    if (tid == 0) g_flags[cta] = (unsigned)(T_STEPS + 1);

    if (cta == 0) {
        if (tid < NBLOCKS) {
            while (g_flags[tid] < (unsigned)(T_STEPS + 1)) { }
        }
        __threadfence();
        __syncthreads();
        if (tid == 0 && avg_out) {
            double c = (double)g_spike_count;
            *avg_out = (float)(c / (double)TBR);
        }
    }
}

extern "C" void kernel_launch(void* const* d_in, const int* in_sizes, int n_in,
                              void* d_out, int out_size) {
    (void)in_sizes; (void)n_in;
    const float* x    = (const float*)d_in[0];   // (64, 500, 1)
    const float* w_in = (const float*)d_in[1];   // (2048, 1)
    const float* W    = (const float*)d_in[2];   // (2048, 2048)
    float* out = (float*)d_out;

    float* spike = nullptr;
    float* mem   = nullptr;
    float* avg   = nullptr;
    const long long tbr = TBR;
    const long long osz = (long long)out_size;

    if (osz == 2 * tbr + 1) {            // [avg, spikes, mem]
        avg = out; spike = out + 1; mem = out + 1 + tbr;
    } else if (osz == 2 * tbr) {         // [spikes, mem]
        spike = out; mem = out + tbr;
    } else if (osz == 1) {               // scalar only
        avg = out;
    } else if (osz > 2 * tbr + 1) {      // unknown but big enough: assume concat
        avg = out; spike = out + 1; mem = out + 1 + tbr;
    } else {
        avg = out;
    }

    static int smem_set = 0;
    if (!smem_set) {
        cudaFuncSetAttribute(snn_kernel,
                             cudaFuncAttributeMaxDynamicSharedMemorySize, SMEM_BYTES);
        smem_set = 1;
    }

    snn_init_kernel<<<1, 256>>>();
    snn_kernel<<<NBLOCKS, NTHREADS, SMEM_BYTES>>>(x, w_in, W, spike, mem, avg);
}

// round 9
// speedup vs baseline: 4.0200x; 1.8983x over previous
#include <cuda_runtime.h>
#include <cstdint>

// ============================================================================
// SpikingReservoirLoaded: B=64, T=500, R=2048, beta=0.9, thr=1.0, zero reset.
//   V_t = beta*V_{t-1} + x[b,t]*w_in[r] + sum_{j: S_{t-1}[b,j]=1} W[j,r]
//
// R8 = R7 with the uint16 overflow fixed: index lists now store the raw row
// index j (<= 2047, fits uint16); the gather shifts by 6 (row stride 64B) at
// the use site. R7 stored j<<6 (up to 131008) in uint16 -> wrapped for
// j>=1024 -> wrong W rows -> divergence. Everything else unchanged:
//  * CTA = 16-col W slice in smem, all 64 batches per CTA (load balance)
//  * masks decoded ONCE per step into per-batch shared index lists
//  * gather: ushort4 idx + 4 independent LDS.64, strict ascending j with a
//    single accumulator pair -> bit-identical fp32 to the verified R6 kernel
//  * per-batch fallback to exact bit-scan if count > CAP_B
//  * release/acquire flag barrier
// ============================================================================

#define T_STEPS   500
#define BATCH     64
#define RSIZE     2048
#define NWORDS32  64                      // 32-bit mask words per batch
#define NBLOCKS   128
#define NTHREADS  512
#define TBR       (500LL * 64LL * 2048LL) // 65,536,000

#define CAP_B     768                     // idx entries per batch (uint16)
#define SMEM_W_BYTES   (RSIZE * 64)                   // 131072 (float2[2048][8])
#define SMEM_IDX_OFF   (SMEM_W_BYTES)                 // bytes
#define SMEM_CNT_OFF   (SMEM_W_BYTES + BATCH * CAP_B * 2)   // 229376
#define SMEM_BYTES     (SMEM_CNT_OFF + BATCH * 4)           // 229632

__device__ unsigned g_masks[2][BATCH][NWORDS32]; // spike bitmasks, ping-pong
__device__ unsigned g_flags[NBLOCKS];            // barrier flags
__device__ unsigned long long g_spike_count;

__global__ void snn_init_kernel() {
    int t = threadIdx.x;
    for (int i = t; i < BATCH * NWORDS32; i += blockDim.x)
        (&g_masks[0][0][0])[i] = 0u;               // S0 = 0 (read at step 0)
    if (t < NBLOCKS) g_flags[t] = 0u;
    if (t == 0) g_spike_count = 0ull;
}

__device__ __forceinline__ void st_release_gpu(unsigned* p, unsigned v) {
    asm volatile("st.release.gpu.global.u32 [%0], %1;" :: "l"(p), "r"(v) : "memory");
}
__device__ __forceinline__ unsigned ld_acquire_gpu(const unsigned* p) {
    unsigned v;
    asm volatile("ld.acquire.gpu.global.u32 %0, [%1];" : "=r"(v) : "l"(p) : "memory");
    return v;
}

__global__ void __launch_bounds__(NTHREADS, 1)
snn_kernel(const float* __restrict__ x,      // (B, T)   [B,T,1]
           const float* __restrict__ w_in,   // (R)
           const float* __restrict__ W,      // (R, R) row-major: W[j*R + r]
           float* __restrict__ spike_out,    // (T,B,R) or null (4B-aligned only!)
           float* __restrict__ mem_out,      // (T,B,R) or null (4B-aligned only!)
           float* avg_out)                   // scalar or null
{
    extern __shared__ char smem[];
    float2* Ws2 = reinterpret_cast<float2*>(smem);                 // [2048][8]
    unsigned short* sidx = reinterpret_cast<unsigned short*>(smem + SMEM_IDX_OFF);
    int* scnt = reinterpret_cast<int*>(smem + SMEM_CNT_OFF);

    const int tid  = threadIdx.x;
    const int cta  = blockIdx.x;
    const int lane = tid & 31;
    const int warp = tid >> 5;
    const int b    = tid >> 3;          // batch 0..63 (gather role)
    const int p    = tid & 7;           // column pair 0..7
    const int col0 = cta * 16 + p * 2;

    // ---- load W column slice into smem (16 cols = 8 float2 per row) ----
    for (int idx = tid; idx < RSIZE * 8; idx += NTHREADS) {
        int j = idx >> 3, q = idx & 7;
        Ws2[j * 8 + q] =
            *reinterpret_cast<const float2*>(W + (size_t)j * RSIZE + cta * 16 + q * 2);
    }

    const float2 win2 = *reinterpret_cast<const float2*>(w_in + col0);
    const float* __restrict__ xb = x + b * T_STEPS;
    const char* wbase = smem + (p << 3);   // + (j<<6) gives &Ws2[j*8+p]

    float2 V = make_float2(0.f, 0.f);
    unsigned cnt = 0;
    const long long recBase = (long long)b * RSIZE + col0;

    for (int t = 0; t < T_STEPS; ++t) {
        // ================= build index lists (warp w -> batches 4w..4w+3) ====
        {
            const unsigned* gm = &g_masks[t & 1][0][0];
            unsigned wreg[4][2];
            #pragma unroll
            for (int q = 0; q < 4; ++q) {
                const unsigned* mb = gm + (warp * 4 + q) * NWORDS32;
                wreg[q][0] = __ldcg(mb + lane);
                wreg[q][1] = __ldcg(mb + 32 + lane);
            }
            #pragma unroll
            for (int q = 0; q < 4; ++q) {
                int bq = warp * 4 + q;
                int base = 0;
                #pragma unroll
                for (int h = 0; h < 2; ++h) {
                    unsigned word = wreg[q][h];
                    int c = __popc(word);
                    int s = c;                      // inclusive scan of popc
                    #pragma unroll
                    for (int d = 1; d < 32; d <<= 1) {
                        int u = __shfl_up_sync(0xffffffffu, s, d);
                        if (lane >= d) s += u;
                    }
                    int pos = base + s - c;
                    int jb = (h * 32 + lane) * 32;
                    unsigned m = word;
                    unsigned short* L = sidx + bq * CAP_B;
                    while (m) {
                        int bit = __ffs(m) - 1;
                        m &= m - 1;
                        if (pos < CAP_B)
                            L[pos] = (unsigned short)(jb + bit);  // raw j (<=2047)
                        ++pos;
                    }
                    base += __shfl_sync(0xffffffffu, s, 31);
                }
                if (lane == 0) scnt[bq] = base;
            }
        }
        __syncthreads();

        // ================= gather: ascending j, single accumulator pair =====
        float ax = 0.f, ay = 0.f;
        {
            int n = scnt[b];
            if (n <= CAP_B) {
                const unsigned short* L = sidx + b * CAP_B;
                int i = 0;
                int n4 = n & ~3;
                #pragma unroll 1
                for (; i < n4; i += 4) {
                    ushort4 o4 = *reinterpret_cast<const ushort4*>(L + i);
                    float2 w0 = *reinterpret_cast<const float2*>(wbase + ((unsigned)o4.x << 6));
                    float2 w1 = *reinterpret_cast<const float2*>(wbase + ((unsigned)o4.y << 6));
                    float2 w2 = *reinterpret_cast<const float2*>(wbase + ((unsigned)o4.z << 6));
                    float2 w3 = *reinterpret_cast<const float2*>(wbase + ((unsigned)o4.w << 6));
                    ax += w0.x; ay += w0.y;
                    ax += w1.x; ay += w1.y;
                    ax += w2.x; ay += w2.y;
                    ax += w3.x; ay += w3.y;
                }
                for (; i < n; ++i) {
                    float2 wv = *reinterpret_cast<const float2*>(wbase + ((unsigned)L[i] << 6));
                    ax += wv.x; ay += wv.y;
                }
            } else {
                // overflow fallback: exact ascending bit-scan from global masks
                const unsigned* mb = &g_masks[t & 1][b][0];
                #pragma unroll 1
                for (int c = 0; c < NWORDS32; ++c) {
                    unsigned m = __ldcg(mb + c);
                    int jb = c << 5;
                    while (m) {
                        int j = jb + (__ffs(m) - 1);
                        m &= m - 1;
                        float2 wv = *reinterpret_cast<const float2*>(wbase + (j << 6));
                        ax += wv.x; ay += wv.y;
                    }
                }
            }
        }

        // ---- LIF update (identical arithmetic to verified R6) ----
        float xv = __ldg(xb + t);
        float v0 = fmaf(0.9f, V.x, xv * win2.x) + ax;
        float v1 = fmaf(0.9f, V.y, xv * win2.y) + ay;
        bool s0 = (v0 >= 1.0f);
        bool s1 = (v1 >= 1.0f);
        V.x = s0 ? 0.f : v0;
        V.y = s1 ? 0.f : v1;
        cnt += (unsigned)s0 + (unsigned)s1;

        // ---- records: SCALAR stores (bases only 4B-aligned) ----
        if (spike_out) {
            long long off = (long long)t * (BATCH * RSIZE) + recBase;
            spike_out[off]     = s0 ? 1.f : 0.f;
            spike_out[off + 1] = s1 ? 1.f : 0.f;
            mem_out[off]     = V.x;
            mem_out[off + 1] = V.y;
        }

        // ---- publish 16-bit spike slice for (b, cta) ----
        unsigned hv = ((unsigned)s0 | ((unsigned)s1 << 1)) << (p * 2);
        hv |= __shfl_xor_sync(0xffffffffu, hv, 1);
        hv |= __shfl_xor_sync(0xffffffffu, hv, 2);
        hv |= __shfl_xor_sync(0xffffffffu, hv, 4);
        if (p == 0) {
            unsigned short* m16 =
                reinterpret_cast<unsigned short*>(&g_masks[(t + 1) & 1][0][0]);
            m16[b * 128 + cta] = (unsigned short)hv;  // word cta/2, half cta&1
        }

        // ---- chip-wide barrier: bar(cta) -> release store -> acquire polls ----
        __syncthreads();
        if (tid == 0) st_release_gpu(&g_flags[cta], (unsigned)(t + 1));
        if (tid < NBLOCKS) {
            while (ld_acquire_gpu(&g_flags[tid]) < (unsigned)(t + 1)) { }
        }
        __syncthreads();
    }

    // ---- global spike count -> average firing rate ----
    #pragma unroll
    for (int s = 16; s; s >>= 1)
        cnt += __shfl_down_sync(0xffffffffu, cnt, s);
    if ((tid & 31) == 0 && cnt) atomicAdd(&g_spike_count, (unsigned long long)cnt);

    __syncthreads();
    if (tid == 0) st_release_gpu(&g_flags[cta], (unsigned)(T_STEPS + 1));

    if (cta == 0) {
        if (tid < NBLOCKS) {
            while (ld_acquire_gpu(&g_flags[tid]) < (unsigned)(T_STEPS + 1)) { }
        }
        __syncthreads();
        if (tid == 0 && avg_out) {
            double c = (double)g_spike_count;
            *avg_out = (float)(c / (double)TBR);
        }
    }
}

extern "C" void kernel_launch(void* const* d_in, const int* in_sizes, int n_in,
                              void* d_out, int out_size) {
    (void)in_sizes; (void)n_in;
    const float* x    = (const float*)d_in[0];   // (64, 500, 1)
    const float* w_in = (const float*)d_in[1];   // (2048, 1)
    const float* W    = (const float*)d_in[2];   // (2048, 2048)
    float* out = (float*)d_out;

    float* spike = nullptr;
    float* mem   = nullptr;
    float* avg   = nullptr;
    const long long tbr = TBR;
    const long long osz = (long long)out_size;

    if (osz == 2 * tbr + 1) {            // [avg, spikes, mem]
        avg = out; spike = out + 1; mem = out + 1 + tbr;
    } else if (osz == 2 * tbr) {         // [spikes, mem]
        spike = out; mem = out + tbr;
    } else if (osz == 1) {               // scalar only
        avg = out;
    } else if (osz > 2 * tbr + 1) {      // unknown but big enough: assume concat
        avg = out; spike = out + 1; mem = out + 1 + tbr;
    } else {
        avg = out;
    }

    static int smem_set = 0;
    if (!smem_set) {
        cudaFuncSetAttribute(snn_kernel,
                             cudaFuncAttributeMaxDynamicSharedMemorySize, SMEM_BYTES);
        smem_set = 1;
    }

    snn_init_kernel<<<1, 256>>>();
    snn_kernel<<<NBLOCKS, NTHREADS, SMEM_BYTES>>>(x, w_in, W, spike, mem, avg);
}

// round 10
// speedup vs baseline: 5.7854x; 1.4392x over previous
#include <cuda_runtime.h>
#include <cstdint>

// ============================================================================
// SpikingReservoirLoaded: B=64, T=500, R=2048, beta=0.9, thr=1.0, zero reset.
//   V_t = beta*V_{t-1} + x[b,t]*w_in[r] + sum_{j: S_{t-1}[b,j]=1} W[j,r]
//
// R9 = R8 with a rebuilt gather engine:
//  * unroll 8: one uint4 (8 ushort idx, 8-way broadcast) + 8 independent
//    LDS.64 row loads + 8 SEQUENTIAL add.rn.f32x2 into one packed
//    accumulator -> same fp32 op sequence per column as the verified
//    kernel (strict ascending j, single accumulator) -> bit-exact.
//  * list overflow (>CAP_B spikes) spills to a global per-(cta,batch)
//    array instead of falling back to the serial bit-rescan -> no more
//    per-step stragglers when firing > 37.5%.
// Unchanged: CTA = 16-col W slice in smem, 64 batches/CTA, decode-once
// index lists, release/acquire flag barrier, scalar record stores.
// ============================================================================

#define T_STEPS   500
#define BATCH     64
#define RSIZE     2048
#define NWORDS32  64
#define NBLOCKS   128
#define NTHREADS  512
#define TBR       (500LL * 64LL * 2048LL) // 65,536,000

#define CAP_B     768                     // smem idx entries per batch
#define OVF_CAP   1280                    // global overflow entries (768+1280=2048)
#define SMEM_W_BYTES   (RSIZE * 64)                   // 131072
#define SMEM_IDX_OFF   (SMEM_W_BYTES)
#define SMEM_CNT_OFF   (SMEM_W_BYTES + BATCH * CAP_B * 2)   // 229376
#define SMEM_BYTES     (SMEM_CNT_OFF + BATCH * 4)           // 229632

__device__ unsigned g_masks[2][BATCH][NWORDS32];
__device__ unsigned g_flags[NBLOCKS];
__device__ unsigned long long g_spike_count;
__device__ unsigned short g_ovf[NBLOCKS][BATCH][OVF_CAP];   // ~21MB overflow lists

__global__ void snn_init_kernel() {
    int t = threadIdx.x;
    for (int i = t; i < BATCH * NWORDS32; i += blockDim.x)
        (&g_masks[0][0][0])[i] = 0u;               // S0 = 0 (read at step 0)
    if (t < NBLOCKS) g_flags[t] = 0u;
    if (t == 0) g_spike_count = 0ull;
}

__device__ __forceinline__ void st_release_gpu(unsigned* p, unsigned v) {
    asm volatile("st.release.gpu.global.u32 [%0], %1;" :: "l"(p), "r"(v) : "memory");
}
__device__ __forceinline__ unsigned ld_acquire_gpu(const unsigned* p) {
    unsigned v;
    asm volatile("ld.acquire.gpu.global.u32 %0, [%1];" : "=r"(v) : "l"(p) : "memory");
    return v;
}
// packed fp32 pair add: per-lane IEEE rn add, bit-identical to scalar FADDs
__device__ __forceinline__ unsigned long long add_f32x2(unsigned long long a,
                                                        unsigned long long b) {
    unsigned long long r;
    asm("add.rn.f32x2 %0, %1, %2;" : "=l"(r) : "l"(a), "l"(b));
    return r;
}

__global__ void __launch_bounds__(NTHREADS, 1)
snn_kernel(const float* __restrict__ x,      // (B, T)   [B,T,1]
           const float* __restrict__ w_in,   // (R)
           const float* __restrict__ W,      // (R, R) row-major: W[j*R + r]
           float* __restrict__ spike_out,    // (T,B,R) or null (4B-aligned only!)
           float* __restrict__ mem_out,      // (T,B,R) or null (4B-aligned only!)
           float* avg_out)                   // scalar or null
{
    extern __shared__ char smem[];
    float2* Ws2 = reinterpret_cast<float2*>(smem);                 // [2048][8]
    unsigned short* sidx = reinterpret_cast<unsigned short*>(smem + SMEM_IDX_OFF);
    int* scnt = reinterpret_cast<int*>(smem + SMEM_CNT_OFF);

    const int tid  = threadIdx.x;
    const int cta  = blockIdx.x;
    const int lane = tid & 31;
    const int warp = tid >> 5;
    const int b    = tid >> 3;          // batch 0..63 (gather role)
    const int p    = tid & 7;           // column pair 0..7
    const int col0 = cta * 16 + p * 2;

    // ---- load W column slice into smem (16 cols = 8 float2 per row) ----
    for (int idx = tid; idx < RSIZE * 8; idx += NTHREADS) {
        int j = idx >> 3, q = idx & 7;
        Ws2[j * 8 + q] =
            *reinterpret_cast<const float2*>(W + (size_t)j * RSIZE + cta * 16 + q * 2);
    }

    const float2 win2 = *reinterpret_cast<const float2*>(w_in + col0);
    const float* __restrict__ xb = x + b * T_STEPS;
    const char* wbase = smem + (p << 3);   // + (j<<6) gives &Ws2[j*8+p]

    float2 V = make_float2(0.f, 0.f);
    unsigned cnt = 0;
    const long long recBase = (long long)b * RSIZE + col0;

    for (int t = 0; t < T_STEPS; ++t) {
        // ================= build index lists (warp w -> batches 4w..4w+3) ====
        {
            const unsigned* gm = &g_masks[t & 1][0][0];
            unsigned wreg[4][2];
            #pragma unroll
            for (int q = 0; q < 4; ++q) {
                const unsigned* mb = gm + (warp * 4 + q) * NWORDS32;
                wreg[q][0] = __ldcg(mb + lane);
                wreg[q][1] = __ldcg(mb + 32 + lane);
            }
            #pragma unroll
            for (int q = 0; q < 4; ++q) {
                int bq = warp * 4 + q;
                int base = 0;
                unsigned short* L = sidx + bq * CAP_B;
                unsigned short* G = &g_ovf[cta][bq][0];
                #pragma unroll
                for (int h = 0; h < 2; ++h) {
                    unsigned word = wreg[q][h];
                    int c = __popc(word);
                    int s = c;                      // inclusive scan of popc
                    #pragma unroll
                    for (int d = 1; d < 32; d <<= 1) {
                        int u = __shfl_up_sync(0xffffffffu, s, d);
                        if (lane >= d) s += u;
                    }
                    int pos = base + s - c;
                    int jb = (h * 32 + lane) * 32;
                    unsigned m = word;
                    while (m) {
                        int bit = __ffs(m) - 1;
                        m &= m - 1;
                        unsigned short jv = (unsigned short)(jb + bit);
                        if (pos < CAP_B) L[pos] = jv;
                        else             G[pos - CAP_B] = jv;
                        ++pos;
                    }
                    base += __shfl_sync(0xffffffffu, s, 31);
                }
                if (lane == 0) scnt[bq] = base;
            }
        }
        __syncthreads();   // also orders the g_ovf global writes CTA-wide

        // ================= gather: ascending j, packed accumulator ==========
        unsigned long long acc = 0ull;   // (ax, ay) as f32x2
        {
            int n  = scnt[b];
            int ns = n < CAP_B ? n : CAP_B;
            const unsigned short* L = sidx + b * CAP_B;
            int i = 0;
            int n8 = ns & ~7;
            #pragma unroll 1
            for (; i < n8; i += 8) {
                uint4 v = *reinterpret_cast<const uint4*>(L + i);  // 8 idx, broadcast
                unsigned o0 = (v.x & 0xffffu) << 6, o1 = (v.x >> 16) << 6;
                unsigned o2 = (v.y & 0xffffu) << 6, o3 = (v.y >> 16) << 6;
                unsigned o4 = (v.z & 0xffffu) << 6, o5 = (v.z >> 16) << 6;
                unsigned o6 = (v.w & 0xffffu) << 6, o7 = (v.w >> 16) << 6;
                unsigned long long r0 = *reinterpret_cast<const unsigned long long*>(wbase + o0);
                unsigned long long r1 = *reinterpret_cast<const unsigned long long*>(wbase + o1);
                unsigned long long r2 = *reinterpret_cast<const unsigned long long*>(wbase + o2);
                unsigned long long r3 = *reinterpret_cast<const unsigned long long*>(wbase + o3);
                unsigned long long r4 = *reinterpret_cast<const unsigned long long*>(wbase + o4);
                unsigned long long r5 = *reinterpret_cast<const unsigned long long*>(wbase + o5);
                unsigned long long r6 = *reinterpret_cast<const unsigned long long*>(wbase + o6);
                unsigned long long r7 = *reinterpret_cast<const unsigned long long*>(wbase + o7);
                acc = add_f32x2(acc, r0);
                acc = add_f32x2(acc, r1);
                acc = add_f32x2(acc, r2);
                acc = add_f32x2(acc, r3);
                acc = add_f32x2(acc, r4);
                acc = add_f32x2(acc, r5);
                acc = add_f32x2(acc, r6);
                acc = add_f32x2(acc, r7);
            }
            for (; i < ns; ++i) {
                unsigned long long r =
                    *reinterpret_cast<const unsigned long long*>(wbase + ((unsigned)L[i] << 6));
                acc = add_f32x2(acc, r);
            }
            if (n > CAP_B) {   // overflow entries from global (ascending continuation)
                const unsigned short* G = &g_ovf[cta][b][0];
                int no = n - CAP_B;
                #pragma unroll 1
                for (int k2 = 0; k2 < no; ++k2) {
                    unsigned long long r =
                        *reinterpret_cast<const unsigned long long*>(wbase + ((unsigned)G[k2] << 6));
                    acc = add_f32x2(acc, r);
                }
            }
        }
        float ax = __uint_as_float((unsigned)(acc & 0xffffffffull));
        float ay = __uint_as_float((unsigned)(acc >> 32));

        // ---- LIF update (identical arithmetic to verified R8) ----
        float xv = __ldg(xb + t);
        float v0 = fmaf(0.9f, V.x, xv * win2.x) + ax;
        float v1 = fmaf(0.9f, V.y, xv * win2.y) + ay;
        bool s0 = (v0 >= 1.0f);
        bool s1 = (v1 >= 1.0f);
        V.x = s0 ? 0.f : v0;
        V.y = s1 ? 0.f : v1;
        cnt += (unsigned)s0 + (unsigned)s1;

        // ---- records: SCALAR stores (bases only 4B-aligned) ----
        if (spike_out) {
            long long off = (long long)t * (BATCH * RSIZE) + recBase;
            spike_out[off]     = s0 ? 1.f : 0.f;
            spike_out[off + 1] = s1 ? 1.f : 0.f;
            mem_out[off]     = V.x;
            mem_out[off + 1] = V.y;
        }

        // ---- publish 16-bit spike slice for (b, cta) ----
        unsigned hv = ((unsigned)s0 | ((unsigned)s1 << 1)) << (p * 2);
        hv |= __shfl_xor_sync(0xffffffffu, hv, 1);
        hv |= __shfl_xor_sync(0xffffffffu, hv, 2);
        hv |= __shfl_xor_sync(0xffffffffu, hv, 4);
        if (p == 0) {
            unsigned short* m16 =
                reinterpret_cast<unsigned short*>(&g_masks[(t + 1) & 1][0][0]);
            m16[b * 128 + cta] = (unsigned short)hv;
        }

        // ---- chip-wide barrier ----
        __syncthreads();
        if (tid == 0) st_release_gpu(&g_flags[cta], (unsigned)(t + 1));
        if (tid < NBLOCKS) {
            while (ld_acquire_gpu(&g_flags[tid]) < (unsigned)(t + 1)) { }
        }
        __syncthreads();
    }

    // ---- global spike count -> average firing rate ----
    #pragma unroll
    for (int s = 16; s; s >>= 1)
        cnt += __shfl_down_sync(0xffffffffu, cnt, s);
    if ((tid & 31) == 0 && cnt) atomicAdd(&g_spike_count, (unsigned long long)cnt);

    __syncthreads();
    if (tid == 0) st_release_gpu(&g_flags[cta], (unsigned)(T_STEPS + 1));

    if (cta == 0) {
        if (tid < NBLOCKS) {
            while (ld_acquire_gpu(&g_flags[tid]) < (unsigned)(T_STEPS + 1)) { }
        }
        __syncthreads();
        if (tid == 0 && avg_out) {
            double c = (double)g_spike_count;
            *avg_out = (float)(c / (double)TBR);
        }
    }
}

extern "C" void kernel_launch(void* const* d_in, const int* in_sizes, int n_in,
                              void* d_out, int out_size) {
    (void)in_sizes; (void)n_in;
    const float* x    = (const float*)d_in[0];   // (64, 500, 1)
    const float* w_in = (const float*)d_in[1];   // (2048, 1)
    const float* W    = (const float*)d_in[2];   // (2048, 2048)
    float* out = (float*)d_out;

    float* spike = nullptr;
    float* mem   = nullptr;
    float* avg   = nullptr;
    const long long tbr = TBR;
    const long long osz = (long long)out_size;

    if (osz == 2 * tbr + 1) {            // [avg, spikes, mem]
        avg = out; spike = out + 1; mem = out + 1 + tbr;
    } else if (osz == 2 * tbr) {         // [spikes, mem]
        spike = out; mem = out + tbr;
    } else if (osz == 1) {               // scalar only
        avg = out;
    } else if (osz > 2 * tbr + 1) {      // unknown but big enough: assume concat
        avg = out; spike = out + 1; mem = out + 1 + tbr;
    } else {
        avg = out;
    }

    static int smem_set = 0;
    if (!smem_set) {
        cudaFuncSetAttribute(snn_kernel,
                             cudaFuncAttributeMaxDynamicSharedMemorySize, SMEM_BYTES);
        smem_set = 1;
    }

    snn_init_kernel<<<1, 256>>>();
    snn_kernel<<<NBLOCKS, NTHREADS, SMEM_BYTES>>>(x, w_in, W, spike, mem, avg);
}